// round 6
// baseline (speedup 1.0000x reference)
#include <cuda_runtime.h>

// Model_35347580846430: reflect-pad depthwise moving average, W=25, PAD=12
// x: [B=64, T=4096, N=128] f32, out same shape.
// out[b,t,n] = mean_{k=-12..12} x[b, reflect(t+k), n]
//
// R6: float2 lanes + CHUNK=128 (traffic ~294MB, proven) + asm-forced
// front-batching of 16 independent loads per BATCH. R3/R4/R5 all came back
// regs=32: ptxas re-serialized every software pipeline, capping per-warp MLP
// at ~4-6. asm volatile ld.global.nc keeps the 16 loads issued back-to-back
// before the serial sum chain consumes them -> 4KB in flight per warp,
// 16MB chip-wide across 4096 warps.

#define B_DIM 64
#define T_DIM 4096
#define N_DIM 128
#define PAD   12
#define WIN   25
#define CHUNK 128         // t-steps per thread
#define CY    2           // chunks per block (blockDim.y)
#define BATCH 8           // software-pipeline width

#define N2 (N_DIM / 2)    // 64 float2 lanes per row

__device__ __forceinline__ int reflect_idx(int t) {
    // np.pad 'reflect': x[-1] -> x[1], x[T] -> x[T-2]
    t = (t < 0) ? -t : t;
    t = (t >= T_DIM) ? (2 * (T_DIM - 1) - t) : t;
    return t;
}

__device__ __forceinline__ float2 ldg_nc_f2(const float2* p) {
    float2 v;
    asm volatile("ld.global.nc.v2.f32 {%0, %1}, [%2];"
                 : "=f"(v.x), "=f"(v.y) : "l"(p));
    return v;
}

__global__ __launch_bounds__(64 * CY)
void ma25_kernel(const float2* __restrict__ x, float2* __restrict__ out) {
    const int tx    = threadIdx.x;                       // 0..63 -> float2 group over N
    const int chunk = blockIdx.x * CY + threadIdx.y;     // which t-chunk
    const int b     = blockIdx.y;
    const int t0    = chunk * CHUNK;

    const float2* __restrict__ xb = x   + (size_t)b * T_DIM * N2 + tx;
    float2*       __restrict__ ob = out + (size_t)b * T_DIM * N2 + tx;

    // Window sum centered at t0-1: t in [t0-13, t0+11].
    // Steady loop then produces outputs for i = 0..CHUNK-1 uniformly.
    float sx = 0.f, sy = 0.f;
    #pragma unroll
    for (int k = -PAD - 1; k <= PAD - 1; k++) {
        int t = reflect_idx(t0 + k);
        float2 v = ldg_nc_f2(xb + (size_t)t * N2);
        sx += v.x; sy += v.y;
    }

    const float inv = 1.0f / (float)WIN;

    for (int i0 = 0; i0 < CHUNK; i0 += BATCH) {
        // Phase 1: 2*BATCH independent loads, order-pinned by asm volatile.
        float2 a[BATCH], d[BATCH];
        #pragma unroll
        for (int j = 0; j < BATCH; j++) {
            const int t = t0 + i0 + j;
            int tin  = t + PAD;      if (tin  >= T_DIM) tin  = 2 * (T_DIM - 1) - tin;
            int tout = t - PAD - 1;  if (tout < 0)      tout = -tout;
            a[j] = ldg_nc_f2(xb + (size_t)tin  * N2);
            d[j] = ldg_nc_f2(xb + (size_t)tout * N2);
        }
        // Phase 2: serial sum chain + stores.
        #pragma unroll
        for (int j = 0; j < BATCH; j++) {
            sx += a[j].x - d[j].x;
            sy += a[j].y - d[j].y;
            float2 o; o.x = sx * inv; o.y = sy * inv;
            ob[(size_t)(t0 + i0 + j) * N2] = o;
        }
    }
}

extern "C" void kernel_launch(void* const* d_in, const int* in_sizes, int n_in,
                              void* d_out, int out_size) {
    const float2* x = (const float2*)d_in[0];
    float2* out = (float2*)d_out;

    dim3 block(64, CY);                            // 128 threads, 4 warps
    dim3 grid(T_DIM / CHUNK / CY, B_DIM);          // (16, 64) = 1024 blocks
    ma25_kernel<<<grid, block>>>(x, out);
}

// round 7
// speedup vs baseline: 1.3408x; 1.3408x over previous
#include <cuda_runtime.h>
#include <cstdint>

// Model_35347580846430: reflect-pad depthwise moving average, W=25, PAD=12
// x: [B=64, T=4096, N=128] f32, out same shape.
// out[b,t,n] = mean_{k=-12..12} x[b, reflect(t+k), n]
//
// R7: cp.async-staged smem tiles. R4/R5/R6 all proved ptxas caps per-warp
// register MLP at ~6 (regs pinned to 32, sum-chain interleaved between loads).
// cp.async has NO destination registers -> structurally unlimited in-flight
// bytes (76KB/block). Compute phase slides the window out of smem (LDS only),
// fully decoupled from the DRAM pipeline.

#define B_DIM  64
#define T_DIM  4096
#define N_DIM  128
#define PAD    12
#define WIN    25
#define T_TILE 128
#define HALO   (2 * PAD)            // 24
#define ROWS   (T_TILE + HALO)      // 152 smem rows
#define N4     (N_DIM / 4)          // 32 float4 per row
#define NTHR   256
#define SMEM_BYTES (ROWS * N_DIM * 4)   // 77824

__device__ __forceinline__ int reflect_idx(int t) {
    // np.pad 'reflect': x[-1] -> x[1], x[T] -> x[T-2]
    t = (t < 0) ? -t : t;
    t = (t >= T_DIM) ? (2 * (T_DIM - 1) - t) : t;
    return t;
}

__global__ __launch_bounds__(NTHR)
void ma25_kernel(const float4* __restrict__ x, float4* __restrict__ out) {
    extern __shared__ float4 smem[];          // [ROWS][N4]

    const int tid  = threadIdx.x;
    const int lane = tid & 31;                // float4 column 0..31
    const int grp  = tid >> 5;                // 0..7
    const int b    = blockIdx.y;
    const int t0   = blockIdx.x * T_TILE;

    const float4* __restrict__ xb = x + (size_t)b * T_DIM * N4 + lane;

    // ---- Load phase: 152 rows, 8 rows per iteration, 19 iterations.
    // Each cp.async: 16B, no destination register -> all 19 in flight.
    #pragma unroll
    for (int it = 0; it < ROWS / 8; it++) {
        const int r = it * 8 + grp;
        const int t = reflect_idx(t0 - PAD + r);
        const float4* src = xb + (size_t)t * N4;
        uint32_t dst = (uint32_t)__cvta_generic_to_shared(&smem[r * N4 + lane]);
        asm volatile("cp.async.cg.shared.global [%0], [%1], 16;"
                     :: "r"(dst), "l"(src) : "memory");
    }
    asm volatile("cp.async.commit_group;" ::: "memory");
    asm volatile("cp.async.wait_group 0;" ::: "memory");
    __syncthreads();

    // ---- Compute phase: each thread owns column `lane`, rows [grp*16, +16).
    // Output row i (global t0+i) uses smem rows i .. i+24.
    const int r0 = grp * 16;
    const float inv = 1.0f / (float)WIN;

    float4* __restrict__ ob = out + (size_t)(b * T_DIM + t0) * N4 + lane;

    // s = sum of smem rows r0 .. r0+23 (24 rows)
    float sx = 0.f, sy = 0.f, sz = 0.f, sw = 0.f;
    #pragma unroll
    for (int j = 0; j < HALO; j++) {
        float4 v = smem[(r0 + j) * N4 + lane];
        sx += v.x; sy += v.y; sz += v.z; sw += v.w;
    }

    #pragma unroll
    for (int i = 0; i < 16; i++) {
        const int r = r0 + i;
        float4 vin = smem[(r + HALO) * N4 + lane];   // row i+24
        float wx = sx + vin.x, wy = sy + vin.y, wz = sz + vin.z, ww = sw + vin.w;

        float4 o; o.x = wx * inv; o.y = wy * inv; o.z = wz * inv; o.w = ww * inv;
        ob[(size_t)r * N4] = o;

        float4 vout = smem[r * N4 + lane];           // row i leaves the window
        sx = wx - vout.x; sy = wy - vout.y; sz = wz - vout.z; sw = ww - vout.w;
    }
}

extern "C" void kernel_launch(void* const* d_in, const int* in_sizes, int n_in,
                              void* d_out, int out_size) {
    const float4* x = (const float4*)d_in[0];
    float4* out = (float4*)d_out;

    cudaFuncSetAttribute(ma25_kernel,
                         cudaFuncAttributeMaxDynamicSharedMemorySize, SMEM_BYTES);

    dim3 block(NTHR);
    dim3 grid(T_DIM / T_TILE, B_DIM);              // (32, 64) = 2048 blocks
    ma25_kernel<<<grid, block, SMEM_BYTES>>>(x, out);
}